// round 2
// baseline (speedup 1.0000x reference)
#include <cuda_runtime.h>
#include <cstdint>

// Causal unbiased-EMA instance norm.
// x: [B, C, T] fp32, lanes = B*C = 2048 contiguous runs of T = 16384.
//   s1 = a*s1 + (1-a)*x ; s2 = a*s2 + (1-a)*x^2 ; w = a*w + (1-a)  (=> 1-a^t)
//   y  = (x - s1/w) * rsqrt(s2/w - (s1/w)^2 + eps)
//      = (w*x - s1) * rsqrt(max(w*s2 - s1^2, 0) + eps*w^2)   (division-free)
//
// Parallelized via truncated warm-up: alpha^1024 = 3.39e-5, so cold-starting
// the EMA state 1024 steps before a chunk's output window matches the full
// recurrence to ~3e-5 relative — far inside the 1e-3 tolerance.
//
// w is tracked as a genuine EMA state (same rounding path as s1/s2) and the
// variance core is clamped to >= 0: at t=1 the true variance is exactly 0 and
// fp32 cancellation can otherwise drive rsqrt's argument negative -> NaN.

#define T_LEN   16384
#define L_CH    1024          // output chunk length per thread
#define W_WARM  1024          // warm-up length
#define N_CH    (T_LEN / L_CH)   // 16 chunks per lane
#define LOG_NCH 4

#define ALPHA_F 0.99f
#define OMA_F   0.01f         // 1 - alpha
#define EPS_F   1e-5f
#define W0_F    0.9999660819f // 1 - alpha^1024

__device__ __forceinline__ float ema_step(float xi, float& s1, float& s2, float& w) {
    float t = OMA_F * xi;
    s1 = fmaf(ALPHA_F, s1, t);
    s2 = fmaf(ALPHA_F, s2, t * xi);
    w  = fmaf(ALPHA_F, w, OMA_F);
    float num   = fmaf(w, xi, -s1);
    float dcore = fmaf(w, s2, -(s1 * s1));
    dcore = fmaxf(dcore, 0.0f);
    float d = fmaf(EPS_F, w * w, dcore);
    float r;
    asm("rsqrt.approx.f32 %0, %1;" : "=f"(r) : "f"(d));
    return num * r;
}

__device__ __forceinline__ void warm_step(float xi, float& s1, float& s2) {
    float t = OMA_F * xi;
    s1 = fmaf(ALPHA_F, s1, t);
    s2 = fmaf(ALPHA_F, s2, t * xi);
}

__global__ void __launch_bounds__(128, 8)
ema_norm_kernel(const float* __restrict__ x, float* __restrict__ y, int nthreads) {
    int tid = blockIdx.x * blockDim.x + threadIdx.x;
    if (tid >= nthreads) return;

    int chunk = tid & (N_CH - 1);
    int lane  = tid >> LOG_NCH;

    const float* xp = x + (size_t)lane * T_LEN + (size_t)chunk * L_CH;
    float*       yp = y + (size_t)lane * T_LEN + (size_t)chunk * L_CH;

    float s1 = 0.0f, s2 = 0.0f, w = 0.0f;

    if (chunk > 0) {
        const float4* wp = reinterpret_cast<const float4*>(xp - W_WARM);
        #pragma unroll 4
        for (int i = 0; i < W_WARM / 4; i++) {
            float4 v = __ldg(wp + i);
            warm_step(v.x, s1, s2);
            warm_step(v.y, s1, s2);
            warm_step(v.z, s1, s2);
            warm_step(v.w, s1, s2);
        }
        w = W0_F;  // 1 - alpha^W_WARM
    }

    const float4* ip = reinterpret_cast<const float4*>(xp);
    float4*       op = reinterpret_cast<float4*>(yp);
    #pragma unroll 4
    for (int i = 0; i < L_CH / 4; i++) {
        float4 v = __ldg(ip + i);
        float4 o;
        o.x = ema_step(v.x, s1, s2, w);
        o.y = ema_step(v.y, s1, s2, w);
        o.z = ema_step(v.z, s1, s2, w);
        o.w = ema_step(v.w, s1, s2, w);
        op[i] = o;
    }
}

extern "C" void kernel_launch(void* const* d_in, const int* in_sizes, int n_in,
                              void* d_out, int out_size) {
    const float* x = (const float*)d_in[0];
    float*       y = (float*)d_out;

    int total  = in_sizes[0];          // B*C*T
    int lanes  = total / T_LEN;        // 2048
    int nthr   = lanes * N_CH;         // 32768

    int block = 128;
    int grid  = (nthr + block - 1) / block;
    ema_norm_kernel<<<grid, block>>>(x, y, nthr);
}

// round 3
// speedup vs baseline: 1.0638x; 1.0638x over previous
#include <cuda_runtime.h>

// Causal unbiased-EMA instance norm, x: [B=8, C=256, T=16384] fp32.
//   s1 = a*s1 + (1-a)*x ; s2 = a*s2 + (1-a)*x^2 ; w -> 1-a^t
//   y  = (w*x - s1) * rsqrt(max(w*s2 - s1^2, 0) + eps*w^2)
//
// Parallelization: each (lane, chunk-of-1024) pair is one thread; the EMA state
// is reconstructed by a truncated warm-up of 768 steps (alpha^768 = 4.4e-4).
//
// All global access is coalesced by staging 32-element-per-thread tiles through
// shared memory (stride-33 padding -> conflict-free STS/LDS both directions).
// The next tile's 32 independent LDGs are issued into registers before the
// current tile's compute (software double-buffer, MLP=32).

#define T_LEN    16384
#define L_CH     1024
#define W_WARM   768
#define N_CH     16           // chunks per lane
#define LANES_PB 8
#define TPB      128          // LANES_PB * N_CH
#define KP       32           // elements per thread per phase
#define PH_WARM  (W_WARM / KP)          // 24
#define PH_TOT   ((W_WARM + L_CH) / KP) // 56
#define SSTR     33           // smem row stride (conflict-free)

#define ALPHA_F 0.99f
#define OMA_F   0.01f
#define EPS_F   1e-5f
#define W0_F    0.99955556f   // 1 - 0.99^768

__device__ __forceinline__ void warm_step(float xi, float& s1, float& s2) {
    float t = OMA_F * xi;
    s1 = fmaf(ALPHA_F, s1, t);
    s2 = fmaf(ALPHA_F, s2, t * xi);
}

__device__ __forceinline__ float ema_step(float xi, float& s1, float& s2, float& w) {
    float t = OMA_F * xi;
    s1 = fmaf(ALPHA_F, s1, t);
    s2 = fmaf(ALPHA_F, s2, t * xi);
    w  = fmaf(ALPHA_F, w, OMA_F);
    float num   = fmaf(w, xi, -s1);
    float dcore = fmaf(w, s2, -(s1 * s1));
    dcore = fmaxf(dcore, 0.0f);            // t=1 cancellation guard (NaN-proof)
    float d = fmaf(EPS_F, w * w, dcore);
    float r;
    asm("rsqrt.approx.f32 %0, %1;" : "=f"(r) : "f"(d));
    return num * r;
}

__global__ void __launch_bounds__(TPB)
ema_norm_kernel(const float* __restrict__ x, float* __restrict__ y)
{
    __shared__ float s_in [TPB * SSTR];
    __shared__ float s_out[TPB * SSTR];
    __shared__ int   s_base[TPB];

    const int tid = threadIdx.x;
    const int ln  = tid & 31;
    const int wb  = (tid >> 5) << 5;        // first seg serviced by this warp
    const int c   = tid & (N_CH - 1);
    const int l   = tid >> 4;
    const int lane_g = blockIdx.x * LANES_PB + l;

    // stream start (may be negative for chunk 0 -> predicated zero-fill)
    s_base[tid] = lane_g * T_LEN + c * L_CH - W_WARM;
    __syncthreads();

    float r[KP];
    float s1 = 0.f, s2 = 0.f, wst = 0.f;
    const int sb = tid * SSTR;

    // ---- tile helpers ----
    #define LOAD_TILE(p) {                                                  \
        _Pragma("unroll")                                                   \
        for (int k = 0; k < KP; k++) {                                      \
            int s = wb + k;                                                 \
            int g = s_base[s] + (p) * KP + ln;                              \
            float v = 0.f;                                                  \
            /* (s & 15)==0 is compile-time per k: only k=0,16 predicate */  \
            if (!(((k & (N_CH - 1)) == 0) && ((p) < PH_WARM)))              \
                v = __ldg(x + g);                                           \
            r[k] = v;                                                       \
        } }

    #define STS_TILE() {                                                    \
        _Pragma("unroll")                                                   \
        for (int k = 0; k < KP; k++)                                        \
            s_in[(wb + k) * SSTR + ln] = r[k];                              \
        }

    #define STORE_TILE(p) {                                                 \
        _Pragma("unroll")                                                   \
        for (int k = 0; k < KP; k++) {                                      \
            int s = wb + k;                                                 \
            int g = s_base[s] + (p) * KP + ln;                              \
            y[g] = s_out[s * SSTR + ln];                                    \
        } }

    // ---- pipeline ----
    LOAD_TILE(0);
    STS_TILE();
    __syncthreads();

    for (int p = 0; p < PH_TOT; p++) {
        if (p + 1 < PH_TOT) LOAD_TILE(p + 1);   // prefetch next tile (MLP=32)

        if (p < PH_WARM) {
            #pragma unroll 8
            for (int i = 0; i < KP; i++)
                warm_step(s_in[sb + i], s1, s2);
        } else {
            if (p == PH_WARM && c != 0) wst = W0_F;   // 1 - alpha^W_WARM
            #pragma unroll 8
            for (int i = 0; i < KP; i++)
                s_out[sb + i] = ema_step(s_in[sb + i], s1, s2, wst);
        }
        __syncthreads();                         // s_out ready; s_in consumed

        if (p >= PH_WARM) STORE_TILE(p);         // coalesced STG
        if (p + 1 < PH_TOT) STS_TILE();          // publish prefetched tile
        __syncthreads();
    }
    #undef LOAD_TILE
    #undef STS_TILE
    #undef STORE_TILE
}

extern "C" void kernel_launch(void* const* d_in, const int* in_sizes, int n_in,
                              void* d_out, int out_size) {
    const float* x = (const float*)d_in[0];
    float*       y = (float*)d_out;

    int total = in_sizes[0];           // B*C*T
    int lanes = total / T_LEN;         // 2048
    int grid  = lanes / LANES_PB;      // 256 blocks of 128 threads

    ema_norm_kernel<<<grid, TPB>>>(x, y);
}

// round 4
// speedup vs baseline: 1.9201x; 1.8050x over previous
#include <cuda_runtime.h>

// Causal unbiased-EMA instance norm, x: [B=8, C=256, T=16384] fp32 — EXACT
// via per-lane block decomposition + affine prefix scan.
//
//   s1 = a*s1 + (1-a)*x ; s2 = a*s2 + (1-a)*x^2 ; w = a*w + (1-a)
//   y  = (w*x - s1) * rsqrt(max(w*s2 - s1^2, 0) + eps*w^2)
//
// One block per (b,c) lane. 256 threads x 64 steps each. The EMA state after
// any 64-step segment is affine in the incoming state with constant decay
// A = a^64, so an affine scan over segment-local sums (v1, v2, multiplier m)
// reconstructs every thread's exact starting state; the multiplier prefix
// a^{t0} also gives the exact bias weight w0 = 1 - a^{t0}.

#define T_LEN  16384
#define TPB    256
#define KP     (T_LEN / TPB)     // 64 steps per thread

#define ALPHA_F 0.99f
#define OMA_F   0.01f
#define EPS_F   1e-5f
#define A64_F   0.52559649f      // 0.99^64

#define PAD(i)  ((i) + ((i) >> 6))           // stride-65 per 64-row padding
#define SMEM_F  (T_LEN + (T_LEN >> 6))       // 16640 floats = 66560 B

__device__ __forceinline__ void warm_step(float xi, float& s1, float& s2) {
    float t = OMA_F * xi;
    s1 = fmaf(ALPHA_F, s1, t);
    s2 = fmaf(ALPHA_F, s2, t * xi);
}

__device__ __forceinline__ float ema_step(float xi, float& s1, float& s2, float& w) {
    float t = OMA_F * xi;
    s1 = fmaf(ALPHA_F, s1, t);
    s2 = fmaf(ALPHA_F, s2, t * xi);
    w  = fmaf(ALPHA_F, w, OMA_F);
    float num   = fmaf(w, xi, -s1);
    float dcore = fmaf(w, s2, -(s1 * s1));
    dcore = fmaxf(dcore, 0.0f);               // t=1 cancellation guard (NaN-proof)
    float d = fmaf(EPS_F, w * w, dcore);
    float r;
    asm("rsqrt.approx.f32 %0, %1;" : "=f"(r) : "f"(d));
    return num * r;
}

extern __shared__ float s_buf[];

__global__ void __launch_bounds__(TPB)
ema_norm_kernel(const float* __restrict__ x, float* __restrict__ y)
{
    __shared__ float tv1[TPB / 32], tv2[TPB / 32], tm[TPB / 32];

    const int tid  = threadIdx.x;
    const int lane = tid & 31;
    const int wid  = tid >> 5;
    const size_t base = (size_t)blockIdx.x * T_LEN;

    // ---- coalesced load into padded smem ----
    #pragma unroll
    for (int i = tid; i < T_LEN; i += TPB)
        s_buf[PAD(i)] = __ldg(x + base + i);
    __syncthreads();

    // ---- pass 1: segment-local EMA sums from zero state ----
    const int t0 = tid * KP;
    float L1 = 0.f, L2 = 0.f;
    #pragma unroll 8
    for (int i = 0; i < KP; i++)
        warm_step(s_buf[PAD(t0 + i)], L1, L2);

    // ---- affine inclusive scan within warp: (v, m) ; combine = vR + mR*vL ----
    float v1 = L1, v2 = L2, m = A64_F;
    #pragma unroll
    for (int d = 1; d < 32; d <<= 1) {
        float pv1 = __shfl_up_sync(0xffffffffu, v1, d);
        float pv2 = __shfl_up_sync(0xffffffffu, v2, d);
        float pm  = __shfl_up_sync(0xffffffffu, m,  d);
        if (lane >= d) {
            v1 = fmaf(m, pv1, v1);
            v2 = fmaf(m, pv2, v2);
            m *= pm;
        }
    }
    // within-warp exclusive
    float ev1 = __shfl_up_sync(0xffffffffu, v1, 1);
    float ev2 = __shfl_up_sync(0xffffffffu, v2, 1);
    float em  = __shfl_up_sync(0xffffffffu, m,  1);
    if (lane == 0) { ev1 = 0.f; ev2 = 0.f; em = 1.f; }

    // cross-warp: publish warp totals, combine serially (8 entries)
    if (lane == 31) { tv1[wid] = v1; tv2[wid] = v2; tm[wid] = m; }
    __syncthreads();
    float p1 = 0.f, p2 = 0.f, pm = 1.f;
    for (int j = 0; j < wid; j++) {          // oldest-first composition
        p1 = fmaf(tm[j], p1, tv1[j]);
        p2 = fmaf(tm[j], p2, tv2[j]);
        pm *= tm[j];
    }
    // thread's exact incoming state: warp-prefix then within-warp-exclusive
    float s1 = fmaf(em, p1, ev1);
    float s2 = fmaf(em, p2, ev2);
    float M  = pm * em;                       // alpha^{t0}, exact to ~8 ulp
    float w  = 1.0f - M;
    __syncthreads();                          // tv/tm consumed before reuse? (none) — protects s_buf timing

    // ---- pass 2: normalize 64 steps from exact state, in-place ----
    #pragma unroll 8
    for (int i = 0; i < KP; i++) {
        int idx = PAD(t0 + i);
        s_buf[idx] = ema_step(s_buf[idx], s1, s2, w);
    }
    __syncthreads();

    // ---- coalesced store ----
    #pragma unroll
    for (int i = tid; i < T_LEN; i += TPB)
        y[base + i] = s_buf[PAD(i)];
}

extern "C" void kernel_launch(void* const* d_in, const int* in_sizes, int n_in,
                              void* d_out, int out_size) {
    const float* x = (const float*)d_in[0];
    float*       y = (float*)d_out;

    int total = in_sizes[0];            // B*C*T
    int lanes = total / T_LEN;          // 2048 blocks, one per lane

    cudaFuncSetAttribute(ema_norm_kernel,
                         cudaFuncAttributeMaxDynamicSharedMemorySize,
                         SMEM_F * sizeof(float));
    ema_norm_kernel<<<lanes, TPB, SMEM_F * sizeof(float)>>>(x, y);
}

// round 5
// speedup vs baseline: 2.5285x; 1.3168x over previous
#include <cuda_runtime.h>
#include <cstdint>

// Causal unbiased-EMA instance norm, x: [B=8, C=256, T=16384] fp32 — EXACT
// via per-lane block decomposition + affine prefix scan.
//
//   s1 = a*s1 + (1-a)*x ; s2 = a*s2 + (1-a)*x^2 ; w = a*w + (1-a)
//   y  = (w*x - s1) * rsqrt(max(w*s2 - s1^2, 0) + eps*w^2)
//
// One block per (b,c) lane, 256 threads x 64 steps. Segment EMA state is
// affine in the incoming state with decay A = a^64 -> affine scan gives each
// thread its exact start state; the multiplier prefix gives w0 = 1 - a^{t0}.
//
// R5: fully vectorized data movement — cp.async.cg (16B) global->smem,
// LDS.128/STS.128 in the passes, LDS.128+STG.128 on output. Padding is 16B
// per 64-float row so float4 alignment survives and all patterns are
// bank-conflict-free.

#define T_LEN  16384
#define TPB    256
#define KP     (T_LEN / TPB)     // 64 steps per thread

#define ALPHA_F 0.99f
#define OMA_F   0.01f
#define EPS_F   1e-5f
#define A64_F   0.52559649f      // 0.99^64

#define PAD(i)  ((i) + (((i) >> 6) << 2))    // +4 floats (16B) per 64-row
#define SMEM_F  (T_LEN + ((T_LEN >> 6) << 2))  // 17408 floats = 69632 B

__device__ __forceinline__ void cp_async16(float* smem_dst, const float* gmem_src) {
    uint32_t s = (uint32_t)__cvta_generic_to_shared(smem_dst);
    asm volatile("cp.async.cg.shared.global [%0], [%1], 16;" :: "r"(s), "l"(gmem_src));
}

__device__ __forceinline__ void warm_step(float xi, float& s1, float& s2) {
    float t = OMA_F * xi;
    s1 = fmaf(ALPHA_F, s1, t);
    s2 = fmaf(ALPHA_F, s2, t * xi);
}

__device__ __forceinline__ float ema_step(float xi, float& s1, float& s2, float& w) {
    float t = OMA_F * xi;
    s1 = fmaf(ALPHA_F, s1, t);
    s2 = fmaf(ALPHA_F, s2, t * xi);
    w  = fmaf(ALPHA_F, w, OMA_F);
    float num   = fmaf(w, xi, -s1);
    float dcore = fmaf(w, s2, -(s1 * s1));
    dcore = fmaxf(dcore, 0.0f);               // t=1 cancellation guard (NaN-proof)
    float d = fmaf(EPS_F, w * w, dcore);
    float r;
    asm("rsqrt.approx.f32 %0, %1;" : "=f"(r) : "f"(d));
    return num * r;
}

extern __shared__ float s_buf[];

__global__ void __launch_bounds__(TPB)
ema_norm_kernel(const float* __restrict__ x, float* __restrict__ y)
{
    __shared__ float tv1[TPB / 32], tv2[TPB / 32], tm[TPB / 32];

    const int tid  = threadIdx.x;
    const int lane = tid & 31;
    const int wid  = tid >> 5;
    const size_t base = (size_t)blockIdx.x * T_LEN;

    // ---- async vector load: 16 x cp.async.cg of 16B per thread ----
    #pragma unroll
    for (int k = 0; k < T_LEN / (TPB * 4); k++) {
        int i4 = 4 * tid + k * (TPB * 4);     // float index, 16B aligned
        cp_async16(s_buf + PAD(i4), x + base + i4);
    }
    asm volatile("cp.async.commit_group;");
    asm volatile("cp.async.wait_group 0;" ::: "memory");
    __syncthreads();

    // ---- pass 1: segment-local EMA sums from zero state (LDS.128) ----
    const int t0 = tid * KP;
    const float4* row = reinterpret_cast<const float4*>(s_buf + PAD(t0));
    float L1 = 0.f, L2 = 0.f;
    #pragma unroll
    for (int i = 0; i < KP / 4; i++) {
        float4 v = row[i];
        warm_step(v.x, L1, L2);
        warm_step(v.y, L1, L2);
        warm_step(v.z, L1, L2);
        warm_step(v.w, L1, L2);
    }

    // ---- affine inclusive scan within warp: (v, m) ; combine = vR + mR*vL ----
    float v1 = L1, v2 = L2, m = A64_F;
    #pragma unroll
    for (int d = 1; d < 32; d <<= 1) {
        float pv1 = __shfl_up_sync(0xffffffffu, v1, d);
        float pv2 = __shfl_up_sync(0xffffffffu, v2, d);
        float pm  = __shfl_up_sync(0xffffffffu, m,  d);
        if (lane >= d) {
            v1 = fmaf(m, pv1, v1);
            v2 = fmaf(m, pv2, v2);
            m *= pm;
        }
    }
    // within-warp exclusive
    float ev1 = __shfl_up_sync(0xffffffffu, v1, 1);
    float ev2 = __shfl_up_sync(0xffffffffu, v2, 1);
    float em  = __shfl_up_sync(0xffffffffu, m,  1);
    if (lane == 0) { ev1 = 0.f; ev2 = 0.f; em = 1.f; }

    // cross-warp: publish warp totals, combine serially (8 entries)
    if (lane == 31) { tv1[wid] = v1; tv2[wid] = v2; tm[wid] = m; }
    __syncthreads();
    float p1 = 0.f, p2 = 0.f, pm = 1.f;
    for (int j = 0; j < wid; j++) {           // oldest-first composition
        p1 = fmaf(tm[j], p1, tv1[j]);
        p2 = fmaf(tm[j], p2, tv2[j]);
        pm *= tm[j];
    }
    float s1 = fmaf(em, p1, ev1);
    float s2 = fmaf(em, p2, ev2);
    float w  = 1.0f - pm * em;                // 1 - alpha^{t0}

    // ---- pass 2: normalize 64 steps from exact state, in-place (128-bit) ----
    float4* rw = reinterpret_cast<float4*>(s_buf + PAD(t0));
    #pragma unroll
    for (int i = 0; i < KP / 4; i++) {
        float4 v = rw[i];
        float4 o;
        o.x = ema_step(v.x, s1, s2, w);
        o.y = ema_step(v.y, s1, s2, w);
        o.z = ema_step(v.z, s1, s2, w);
        o.w = ema_step(v.w, s1, s2, w);
        rw[i] = o;
    }
    __syncthreads();

    // ---- vector store: LDS.128 + STG.128, coalesced ----
    #pragma unroll
    for (int k = 0; k < T_LEN / (TPB * 4); k++) {
        int i4 = 4 * tid + k * (TPB * 4);
        float4 v = *reinterpret_cast<const float4*>(s_buf + PAD(i4));
        *reinterpret_cast<float4*>(y + base + i4) = v;
    }
}

extern "C" void kernel_launch(void* const* d_in, const int* in_sizes, int n_in,
                              void* d_out, int out_size) {
    const float* x = (const float*)d_in[0];
    float*       y = (float*)d_out;

    int total = in_sizes[0];            // B*C*T
    int lanes = total / T_LEN;          // 2048 blocks, one per lane

    cudaFuncSetAttribute(ema_norm_kernel,
                         cudaFuncAttributeMaxDynamicSharedMemorySize,
                         SMEM_F * sizeof(float));
    ema_norm_kernel<<<lanes, TPB, SMEM_F * sizeof(float)>>>(x, y);
}